// round 6
// baseline (speedup 1.0000x reference)
#include <cuda_runtime.h>
#include <cuda_fp16.h>
#include <cstdint>

// ---------------------------------------------------------------------------
// Problem dims
// ---------------------------------------------------------------------------
static constexpr int T_ = 8192;   // tokens (M)
static constexpr int O_ = 4096;   // out features (N)
static constexpr int I_ = 4096;   // in features (K)
static constexpr int G_ = I_ / 256;

// ---------------------------------------------------------------------------
// Scratch (device globals — no runtime allocation allowed)
// ---------------------------------------------------------------------------
__device__ __half g_xq[(size_t)T_ * I_];   // (q - zp), exact integer in fp16
__device__ __half g_wq[(size_t)O_ * I_];   // (w - z) * s in fp16
__device__ float  g_sx[T_];                // per-token activation scale

// ---------------------------------------------------------------------------
// PTX helpers (classic path; tcgen05 not available: toolchain targets sm_103)
// ---------------------------------------------------------------------------
__device__ __forceinline__ void cp_async16(uint32_t saddr, const void* gptr) {
    asm volatile("cp.async.cg.shared.global [%0], [%1], 16;\n"
                 :: "r"(saddr), "l"(gptr) : "memory");
}
__device__ __forceinline__ void cp_commit() {
    asm volatile("cp.async.commit_group;\n" ::: "memory");
}
template <int N>
__device__ __forceinline__ void cp_wait() {
    asm volatile("cp.async.wait_group %0;\n" :: "n"(N) : "memory");
}
__device__ __forceinline__ uint32_t smem_u32(const void* p) {
    uint32_t a;
    asm("{ .reg .u64 t; cvta.to.shared.u64 t, %1; cvt.u32.u64 %0, t; }"
        : "=r"(a) : "l"(p));
    return a;
}
__device__ __forceinline__ void ldmatrix_x4(uint32_t (&r)[4], uint32_t addr) {
    asm volatile("ldmatrix.sync.aligned.m8n8.x4.shared.b16 {%0,%1,%2,%3}, [%4];\n"
                 : "=r"(r[0]), "=r"(r[1]), "=r"(r[2]), "=r"(r[3]) : "r"(addr));
}
// fp16-accumulator HMMA: D(f16x2 x2) += A(f16 16x16) * B(f16 16x8)
__device__ __forceinline__ void mma16816_f16(uint32_t (&d)[2], const uint32_t (&a)[4],
                                             uint32_t b0, uint32_t b1) {
    asm volatile(
        "mma.sync.aligned.m16n8k16.row.col.f16.f16.f16.f16 "
        "{%0,%1}, {%2,%3,%4,%5}, {%6,%7}, {%0,%1};\n"
        : "+r"(d[0]), "+r"(d[1])
        : "r"(a[0]), "r"(a[1]), "r"(a[2]), "r"(a[3]), "r"(b0), "r"(b1));
}

// ---------------------------------------------------------------------------
// Kernel 1: per-token asymmetric int8 fake-quant of x (exact vs reference).
// ---------------------------------------------------------------------------
__global__ void __launch_bounds__(256) quant_x_kernel(const float* __restrict__ x) {
    const int row = blockIdx.x;
    const int tid = threadIdx.x;
    const float4* xr = reinterpret_cast<const float4*>(x) + (size_t)row * (I_ / 4);

    float4 v[4];
    float mn = 0.0f, mx = 0.0f;
#pragma unroll
    for (int j = 0; j < 4; ++j) {
        v[j] = xr[tid + 256 * j];
        mn = fminf(mn, fminf(fminf(v[j].x, v[j].y), fminf(v[j].z, v[j].w)));
        mx = fmaxf(mx, fmaxf(fmaxf(v[j].x, v[j].y), fmaxf(v[j].z, v[j].w)));
    }
#pragma unroll
    for (int o = 16; o > 0; o >>= 1) {
        mn = fminf(mn, __shfl_xor_sync(0xffffffffu, mn, o));
        mx = fmaxf(mx, __shfl_xor_sync(0xffffffffu, mx, o));
    }
    __shared__ float smn[8], smx[8];
    if ((tid & 31) == 0) { smn[tid >> 5] = mn; smx[tid >> 5] = mx; }
    __syncthreads();
    mn = smn[0]; mx = smx[0];
#pragma unroll
    for (int w = 1; w < 8; ++w) { mn = fminf(mn, smn[w]); mx = fmaxf(mx, smx[w]); }

    const float scale = fmaxf(__fdiv_rn(mx - mn, 255.0f), 1.1920929e-07f);
    const float dmin = __fdiv_rn(mn, scale);
    const float dmax = __fdiv_rn(mx, scale);
    float zp = ((-128.0f + dmin) + (127.0f + dmax) > 0.0f) ? (-128.0f - dmin)
                                                           : (127.0f - dmax);
    zp = rintf(fminf(fmaxf(zp, -128.0f), 127.0f));

    __half* out = g_xq + (size_t)row * I_;
#pragma unroll
    for (int j = 0; j < 4; ++j) {
        float f[4] = {v[j].x, v[j].y, v[j].z, v[j].w};
        __align__(8) __half h[4];
#pragma unroll
        for (int e = 0; e < 4; ++e) {
            float q = rintf(__fdiv_rn(f[e], scale)) + zp;
            q = fminf(fmaxf(q, -128.0f), 127.0f);
            h[e] = __float2half_rn(q - zp);   // integer in [-255,255]: exact
        }
        *reinterpret_cast<uint2*>(out + (size_t)(tid + 256 * j) * 4) =
            *reinterpret_cast<const uint2*>(h);
    }
    if (tid == 0) g_sx[row] = scale;
}

// ---------------------------------------------------------------------------
// Kernel 2: groupwise int4 weight dequant -> fp16.
// ---------------------------------------------------------------------------
__global__ void __launch_bounds__(256) dequant_w_kernel(const int* __restrict__ w,
                                                        const float* __restrict__ scales,
                                                        const float* __restrict__ zeros) {
    const int t = blockIdx.x * 256 + threadIdx.x;
    const int row = t >> 9;
    const int col = (t & 511) << 3;
    const int g = col >> 8;
    const float s = scales[row * G_ + g];
    const float z = zeros[row * G_ + g];
    const int4* wp = reinterpret_cast<const int4*>(w + (size_t)row * I_ + col);
    const int4 a = wp[0], b = wp[1];
    __align__(16) __half h[8];
    h[0] = __float2half_rn(((float)a.x - z) * s);
    h[1] = __float2half_rn(((float)a.y - z) * s);
    h[2] = __float2half_rn(((float)a.z - z) * s);
    h[3] = __float2half_rn(((float)a.w - z) * s);
    h[4] = __float2half_rn(((float)b.x - z) * s);
    h[5] = __float2half_rn(((float)b.y - z) * s);
    h[6] = __float2half_rn(((float)b.z - z) * s);
    h[7] = __float2half_rn(((float)b.w - z) * s);
    *reinterpret_cast<uint4*>(g_wq + (size_t)row * I_ + col) =
        *reinterpret_cast<const uint4*>(h);
}

// ---------------------------------------------------------------------------
// Kernel 3: fp16-accum HMMA GEMM  C[t,o] = sx[t] * sum_k xq[t,k] * wq[o,k]
// 128(M) x 256(N) CTA tile, BK=64, 4-stage cp.async pipeline,
// 8 warps (2x4, 64x64 warp tiles). fp16 accumulation over one BK=64 segment
// (4 mma steps), promoted into fp32 accumulators each k-iteration.
// ---------------------------------------------------------------------------
static constexpr int BM = 128;
static constexpr int BN = 256;
static constexpr int BK = 64;                  // halves per stage = 128B rows
static constexpr int STAGES = 4;
static constexpr int NUM_KT = I_ / BK;         // 64 iterations
static constexpr int A_ST = BM * 128;          // 16 KB
static constexpr int B_ST = BN * 128;          // 32 KB
static constexpr int ST = A_ST + B_ST;         // 48 KB per stage
static constexpr int GEMM_SMEM = STAGES * ST + 256;   // ~192.25 KB

__device__ __forceinline__ uint32_t swz(uint32_t row, uint32_t ch) {
    return row * 128u + ((ch ^ (row & 7u)) << 4);
}

__global__ void __launch_bounds__(256, 1) gemm_kernel(float* __restrict__ C) {
    extern __shared__ char dsm[];
    const uint32_t sbase = (smem_u32(dsm) + 127u) & ~127u;

    const int tid = threadIdx.x;
    const int lane = tid & 31;
    const int wid = tid >> 5;
    const int wm = wid >> 2;      // 0..1 : 64-row band
    const int wn = wid & 3;       // 0..3 : 64-col band

    const int m0 = blockIdx.y * BM;
    const int n0 = blockIdx.x * BN;

    const __half* Ag = g_xq + (size_t)m0 * I_;
    const __half* Bg = g_wq + (size_t)n0 * I_;

    float    facc[4][8][4];       // fp32 running sums
    uint32_t hacc[4][8][2];       // fp16x2 mma accumulators (one BK segment)
#pragma unroll
    for (int a = 0; a < 4; ++a)
#pragma unroll
        for (int b = 0; b < 8; ++b) {
#pragma unroll
            for (int c = 0; c < 4; ++c) facc[a][b][c] = 0.0f;
            hacc[a][b][0] = 0u; hacc[a][b][1] = 0u;
        }

    // Producer: 3072 x 16B chunks per stage (A:1024, B:2048); 12 per thread.
    auto issue_loads = [&](int s) {
        const uint32_t sa = sbase + (s % STAGES) * ST;
        const int kcol = s * BK;
#pragma unroll
        for (int i = 0; i < 12; ++i) {
            const int c = tid + i * 256;
            if (c < 1024) {                      // A: 128 rows x 8 chunks
                const int row = c >> 3, ch = c & 7;
                cp_async16(sa + swz(row, ch),
                           Ag + (size_t)row * I_ + kcol + ch * 8);
            } else {                             // B: 256 rows x 8 chunks
                const int c2 = c - 1024;
                const int row = c2 >> 3, ch = c2 & 7;
                cp_async16(sa + A_ST + swz(row, ch),
                           Bg + (size_t)row * I_ + kcol + ch * 8);
            }
        }
        cp_commit();
    };

    issue_loads(0);
    issue_loads(1);
    issue_loads(2);

    for (int s = 0; s < NUM_KT; ++s) {
        cp_wait<2>();                            // stage s resident
        __syncthreads();                         // + reads of buf (s+3)%4 done
        if (s + 3 < NUM_KT) issue_loads(s + 3);
        else cp_commit();                        // uniform group accounting

        const uint32_t bA = sbase + (s % STAGES) * ST;
        const uint32_t bB = bA + A_ST;

#pragma unroll
        for (int ks = 0; ks < 4; ++ks) {         // 4 x K=16 per stage
            uint32_t afr[4][4];
#pragma unroll
            for (int mi = 0; mi < 4; ++mi) {
                const uint32_t row = wm * 64 + mi * 16 + (lane & 15);
                const uint32_t ch = ks * 2 + ((lane >> 4) & 1);
                ldmatrix_x4(afr[mi], bA + swz(row, ch));
            }
            uint32_t bfr[4][4];
#pragma unroll
            for (int np = 0; np < 4; ++np) {
                const uint32_t row =
                    wn * 64 + np * 16 + (lane & 7) + (((lane >> 4) & 1) << 3);
                const uint32_t ch = ks * 2 + ((lane >> 3) & 1);
                ldmatrix_x4(bfr[np], bB + swz(row, ch));
            }
#pragma unroll
            for (int mi = 0; mi < 4; ++mi)
#pragma unroll
                for (int ni = 0; ni < 8; ++ni)
                    mma16816_f16(hacc[mi][ni], afr[mi],
                                 bfr[ni >> 1][(ni & 1) * 2],
                                 bfr[ni >> 1][(ni & 1) * 2 + 1]);
        }

        // Promote this 64-K segment to fp32 (idle FMA pipe; overlaps tensor).
#pragma unroll
        for (int mi = 0; mi < 4; ++mi)
#pragma unroll
            for (int ni = 0; ni < 8; ++ni) {
                const float2 f0 = __half22float2(
                    *reinterpret_cast<__half2*>(&hacc[mi][ni][0]));
                const float2 f1 = __half22float2(
                    *reinterpret_cast<__half2*>(&hacc[mi][ni][1]));
                facc[mi][ni][0] += f0.x; facc[mi][ni][1] += f0.y;
                facc[mi][ni][2] += f1.x; facc[mi][ni][3] += f1.y;
                hacc[mi][ni][0] = 0u;    hacc[mi][ni][1] = 0u;
            }
    }

    // Epilogue: y = sx[row] * facc, fp32 stores
#pragma unroll
    for (int mi = 0; mi < 4; ++mi) {
        const int grow = m0 + wm * 64 + mi * 16 + (lane >> 2);
        const float s0 = g_sx[grow];
        const float s1 = g_sx[grow + 8];
#pragma unroll
        for (int ni = 0; ni < 8; ++ni) {
            const int gcol = n0 + wn * 64 + ni * 8 + (lane & 3) * 2;
            float2 v0, v1;
            v0.x = facc[mi][ni][0] * s0; v0.y = facc[mi][ni][1] * s0;
            v1.x = facc[mi][ni][2] * s1; v1.y = facc[mi][ni][3] * s1;
            *reinterpret_cast<float2*>(C + (size_t)grow * O_ + gcol) = v0;
            *reinterpret_cast<float2*>(C + (size_t)(grow + 8) * O_ + gcol) = v1;
        }
    }
}

// ---------------------------------------------------------------------------
// Launch
// ---------------------------------------------------------------------------
extern "C" void kernel_launch(void* const* d_in, const int* in_sizes, int n_in,
                              void* d_out, int out_size) {
    const float* x = (const float*)d_in[0];
    const int* w = (const int*)d_in[1];
    const float* scales = (const float*)d_in[2];
    const float* zeros = (const float*)d_in[3];
    float* out = (float*)d_out;

    static bool attr_done = false;
    if (!attr_done) {
        cudaFuncSetAttribute(gemm_kernel,
                             cudaFuncAttributeMaxDynamicSharedMemorySize,
                             GEMM_SMEM);
        attr_done = true;
    }

    quant_x_kernel<<<T_, 256>>>(x);
    dequant_w_kernel<<<(O_ * (I_ / 8)) / 256, 256>>>(w, scales, zeros);
    gemm_kernel<<<dim3(O_ / BN, T_ / BM), 256, GEMM_SMEM>>>(out);
}

// round 7
// speedup vs baseline: 1.2343x; 1.2343x over previous
#include <cuda_runtime.h>
#include <cuda_fp16.h>
#include <cstdint>

// ---------------------------------------------------------------------------
// Problem dims
// ---------------------------------------------------------------------------
static constexpr int T_ = 8192;   // tokens (M)
static constexpr int O_ = 4096;   // out features (N)
static constexpr int I_ = 4096;   // in features (K)
static constexpr int G_ = I_ / 256;

// ---------------------------------------------------------------------------
// Scratch (device globals — no runtime allocation allowed)
// ---------------------------------------------------------------------------
__device__ __half g_xq[(size_t)T_ * I_];   // (q - zp), exact integer in fp16
__device__ __half g_wq[(size_t)O_ * I_];   // (w - z) * s in fp16
__device__ float  g_sx[T_];                // per-token activation scale

// ---------------------------------------------------------------------------
// PTX helpers (classic path; tcgen05 not available: toolchain targets sm_103)
// ---------------------------------------------------------------------------
__device__ __forceinline__ void cp_async16(uint32_t saddr, const void* gptr) {
    asm volatile("cp.async.cg.shared.global [%0], [%1], 16;\n"
                 :: "r"(saddr), "l"(gptr) : "memory");
}
__device__ __forceinline__ void cp_commit() {
    asm volatile("cp.async.commit_group;\n" ::: "memory");
}
template <int N>
__device__ __forceinline__ void cp_wait() {
    asm volatile("cp.async.wait_group %0;\n" :: "n"(N) : "memory");
}
__device__ __forceinline__ uint32_t smem_u32(const void* p) {
    uint32_t a;
    asm("{ .reg .u64 t; cvta.to.shared.u64 t, %1; cvt.u32.u64 %0, t; }"
        : "=r"(a) : "l"(p));
    return a;
}
__device__ __forceinline__ void ldmatrix_x4(uint32_t (&r)[4], uint32_t addr) {
    asm volatile("ldmatrix.sync.aligned.m8n8.x4.shared.b16 {%0,%1,%2,%3}, [%4];\n"
                 : "=r"(r[0]), "=r"(r[1]), "=r"(r[2]), "=r"(r[3]) : "r"(addr));
}
__device__ __forceinline__ void mma16816(float (&d)[4], const uint32_t (&a)[4],
                                         uint32_t b0, uint32_t b1) {
    asm volatile(
        "mma.sync.aligned.m16n8k16.row.col.f32.f16.f16.f32 "
        "{%0,%1,%2,%3}, {%4,%5,%6,%7}, {%8,%9}, {%0,%1,%2,%3};\n"
        : "+f"(d[0]), "+f"(d[1]), "+f"(d[2]), "+f"(d[3])
        : "r"(a[0]), "r"(a[1]), "r"(a[2]), "r"(a[3]), "r"(b0), "r"(b1));
}

// ---------------------------------------------------------------------------
// Kernel 1: per-token asymmetric int8 fake-quant of x (exact vs reference).
// ---------------------------------------------------------------------------
__global__ void __launch_bounds__(256) quant_x_kernel(const float* __restrict__ x) {
    const int row = blockIdx.x;
    const int tid = threadIdx.x;
    const float4* xr = reinterpret_cast<const float4*>(x) + (size_t)row * (I_ / 4);

    float4 v[4];
    float mn = 0.0f, mx = 0.0f;
#pragma unroll
    for (int j = 0; j < 4; ++j) {
        v[j] = xr[tid + 256 * j];
        mn = fminf(mn, fminf(fminf(v[j].x, v[j].y), fminf(v[j].z, v[j].w)));
        mx = fmaxf(mx, fmaxf(fmaxf(v[j].x, v[j].y), fmaxf(v[j].z, v[j].w)));
    }
#pragma unroll
    for (int o = 16; o > 0; o >>= 1) {
        mn = fminf(mn, __shfl_xor_sync(0xffffffffu, mn, o));
        mx = fmaxf(mx, __shfl_xor_sync(0xffffffffu, mx, o));
    }
    __shared__ float smn[8], smx[8];
    if ((tid & 31) == 0) { smn[tid >> 5] = mn; smx[tid >> 5] = mx; }
    __syncthreads();
    mn = smn[0]; mx = smx[0];
#pragma unroll
    for (int w = 1; w < 8; ++w) { mn = fminf(mn, smn[w]); mx = fmaxf(mx, smx[w]); }

    const float scale = fmaxf(__fdiv_rn(mx - mn, 255.0f), 1.1920929e-07f);
    const float dmin = __fdiv_rn(mn, scale);
    const float dmax = __fdiv_rn(mx, scale);
    float zp = ((-128.0f + dmin) + (127.0f + dmax) > 0.0f) ? (-128.0f - dmin)
                                                           : (127.0f - dmax);
    zp = rintf(fminf(fmaxf(zp, -128.0f), 127.0f));

    __half* out = g_xq + (size_t)row * I_;
#pragma unroll
    for (int j = 0; j < 4; ++j) {
        float f[4] = {v[j].x, v[j].y, v[j].z, v[j].w};
        __align__(8) __half h[4];
#pragma unroll
        for (int e = 0; e < 4; ++e) {
            float q = rintf(__fdiv_rn(f[e], scale)) + zp;
            q = fminf(fmaxf(q, -128.0f), 127.0f);
            h[e] = __float2half_rn(q - zp);   // integer in [-255,255]: exact
        }
        *reinterpret_cast<uint2*>(out + (size_t)(tid + 256 * j) * 4) =
            *reinterpret_cast<const uint2*>(h);
    }
    if (tid == 0) g_sx[row] = scale;
}

// ---------------------------------------------------------------------------
// Kernel 2: groupwise int4 weight dequant -> fp16.
// ---------------------------------------------------------------------------
__global__ void __launch_bounds__(256) dequant_w_kernel(const int* __restrict__ w,
                                                        const float* __restrict__ scales,
                                                        const float* __restrict__ zeros) {
    const int t = blockIdx.x * 256 + threadIdx.x;
    const int row = t >> 9;
    const int col = (t & 511) << 3;
    const int g = col >> 8;
    const float s = scales[row * G_ + g];
    const float z = zeros[row * G_ + g];
    const int4* wp = reinterpret_cast<const int4*>(w + (size_t)row * I_ + col);
    const int4 a = wp[0], b = wp[1];
    __align__(16) __half h[8];
    h[0] = __float2half_rn(((float)a.x - z) * s);
    h[1] = __float2half_rn(((float)a.y - z) * s);
    h[2] = __float2half_rn(((float)a.z - z) * s);
    h[3] = __float2half_rn(((float)a.w - z) * s);
    h[4] = __float2half_rn(((float)b.x - z) * s);
    h[5] = __float2half_rn(((float)b.y - z) * s);
    h[6] = __float2half_rn(((float)b.z - z) * s);
    h[7] = __float2half_rn(((float)b.w - z) * s);
    *reinterpret_cast<uint4*>(g_wq + (size_t)row * I_ + col) =
        *reinterpret_cast<const uint4*>(h);
}

// ---------------------------------------------------------------------------
// Kernel 3: fp16 HMMA GEMM  C[t,o] = sx[t] * sum_k xq[t,k] * wq[o,k]
// 128x128 CTA tile, BK=64, 3-stage cp.async pipeline, 128 threads
// (4 warps as 2x2, 64x64 warp tiles), 2 CTAs/SM. All load addresses hoisted.
// ---------------------------------------------------------------------------
static constexpr int BM = 128;
static constexpr int BN = 128;
static constexpr int BK = 64;                  // halves per stage = 128B rows
static constexpr int STAGES = 3;
static constexpr int NUM_KT = I_ / BK;         // 64 iterations
static constexpr int A_ST = BM * 128;          // 16 KB
static constexpr int ST = 2 * A_ST;            // 32 KB per stage (A+B)
static constexpr int GEMM_SMEM = STAGES * ST + 256;   // ~96.25 KB -> 2 CTAs/SM

__device__ __forceinline__ uint32_t swz(uint32_t row, uint32_t ch) {
    return row * 128u + ((ch ^ (row & 7u)) << 4);
}

__global__ void __launch_bounds__(128, 2) gemm_kernel(float* __restrict__ C) {
    extern __shared__ char dsm[];
    const uint32_t sbase = (smem_u32(dsm) + 127u) & ~127u;

    const int tid = threadIdx.x;
    const int lane = tid & 31;
    const int wid = tid >> 5;
    const int wm = wid >> 1;      // 0..1 : 64-row band
    const int wn = wid & 1;       // 0..1 : 64-col band

    const int m0 = blockIdx.y * BM;
    const int n0 = blockIdx.x * BN;

    // ---- hoisted producer addressing -------------------------------------
    // A and B stage tiles have the identical 1024-chunk pattern; each of the
    // 128 threads owns 8 chunks of each. Global element offsets and swizzled
    // SMEM offsets are loop-invariant.
    uint32_t goff[8], soff[8];
#pragma unroll
    for (int i = 0; i < 8; ++i) {
        const int c = tid + i * 128;          // 0..1023
        const int row = c >> 3, ch = c & 7;
        goff[i] = (uint32_t)(row * I_ + ch * 8);
        soff[i] = swz(row, ch);
    }
    const __half* Ag = g_xq + (size_t)m0 * I_;   // advanced by BK per stage
    const __half* Bg = g_wq + (size_t)n0 * I_;

    // ---- hoisted consumer (ldmatrix) row terms ---------------------------
    const uint32_t arow[4] = {
        (uint32_t)(wm * 64 +  0 + (lane & 15)), (uint32_t)(wm * 64 + 16 + (lane & 15)),
        (uint32_t)(wm * 64 + 32 + (lane & 15)), (uint32_t)(wm * 64 + 48 + (lane & 15))};
    const uint32_t brow[4] = {
        (uint32_t)(wn * 64 +  0 + (lane & 7) + (((lane >> 4) & 1) << 3)),
        (uint32_t)(wn * 64 + 16 + (lane & 7) + (((lane >> 4) & 1) << 3)),
        (uint32_t)(wn * 64 + 32 + (lane & 7) + (((lane >> 4) & 1) << 3)),
        (uint32_t)(wn * 64 + 48 + (lane & 7) + (((lane >> 4) & 1) << 3))};
    const uint32_t acbit = (lane >> 4) & 1;   // A chunk low bit
    const uint32_t bcbit = (lane >> 3) & 1;   // B chunk low bit

    float acc[4][8][4];
#pragma unroll
    for (int a = 0; a < 4; ++a)
#pragma unroll
        for (int b = 0; b < 8; ++b)
#pragma unroll
            for (int c = 0; c < 4; ++c) acc[a][b][c] = 0.0f;

    auto issue_loads = [&](int s) {
        const uint32_t sa = sbase + (s % STAGES) * ST;
        const __half* As = Ag + s * BK;
        const __half* Bs = Bg + s * BK;
#pragma unroll
        for (int i = 0; i < 8; ++i) {
            cp_async16(sa + soff[i],        As + goff[i]);
            cp_async16(sa + A_ST + soff[i], Bs + goff[i]);
        }
        cp_commit();
    };

    issue_loads(0);
    issue_loads(1);

    for (int s = 0; s < NUM_KT; ++s) {
        cp_wait<1>();                            // stage s resident
        __syncthreads();                         // + reads of buf (s+2)%3 done
        if (s + 2 < NUM_KT) issue_loads(s + 2);
        else cp_commit();                        // uniform group accounting

        const uint32_t bA = sbase + (s % STAGES) * ST;
        const uint32_t bB = bA + A_ST;

#pragma unroll
        for (int ks = 0; ks < 4; ++ks) {         // 4 x K=16 per stage
            uint32_t afr[4][4];
#pragma unroll
            for (int mi = 0; mi < 4; ++mi) {
                const uint32_t ch = ks * 2 + acbit;
                ldmatrix_x4(afr[mi],
                            bA + arow[mi] * 128 + ((ch ^ (arow[mi] & 7)) << 4));
            }
            uint32_t bfr[4][4];
#pragma unroll
            for (int np = 0; np < 4; ++np) {
                const uint32_t ch = ks * 2 + bcbit;
                ldmatrix_x4(bfr[np],
                            bB + brow[np] * 128 + ((ch ^ (brow[np] & 7)) << 4));
            }
#pragma unroll
            for (int mi = 0; mi < 4; ++mi)
#pragma unroll
                for (int ni = 0; ni < 8; ++ni)
                    mma16816(acc[mi][ni], afr[mi],
                             bfr[ni >> 1][(ni & 1) * 2],
                             bfr[ni >> 1][(ni & 1) * 2 + 1]);
        }
    }

    // Epilogue: y = sx[row] * acc, fp32 stores
#pragma unroll
    for (int mi = 0; mi < 4; ++mi) {
        const int grow = m0 + wm * 64 + mi * 16 + (lane >> 2);
        const float s0 = g_sx[grow];
        const float s1 = g_sx[grow + 8];
#pragma unroll
        for (int ni = 0; ni < 8; ++ni) {
            const int gcol = n0 + wn * 64 + ni * 8 + (lane & 3) * 2;
            float2 v0, v1;
            v0.x = acc[mi][ni][0] * s0; v0.y = acc[mi][ni][1] * s0;
            v1.x = acc[mi][ni][2] * s1; v1.y = acc[mi][ni][3] * s1;
            *reinterpret_cast<float2*>(C + (size_t)grow * O_ + gcol) = v0;
            *reinterpret_cast<float2*>(C + (size_t)(grow + 8) * O_ + gcol) = v1;
        }
    }
}

// ---------------------------------------------------------------------------
// Launch
// ---------------------------------------------------------------------------
extern "C" void kernel_launch(void* const* d_in, const int* in_sizes, int n_in,
                              void* d_out, int out_size) {
    const float* x = (const float*)d_in[0];
    const int* w = (const int*)d_in[1];
    const float* scales = (const float*)d_in[2];
    const float* zeros = (const float*)d_in[3];
    float* out = (float*)d_out;

    static bool attr_done = false;
    if (!attr_done) {
        cudaFuncSetAttribute(gemm_kernel,
                             cudaFuncAttributeMaxDynamicSharedMemorySize,
                             GEMM_SMEM);
        attr_done = true;
    }

    quant_x_kernel<<<T_, 256>>>(x);
    dequant_w_kernel<<<(O_ * (I_ / 8)) / 256, 256>>>(w, scales, zeros);
    gemm_kernel<<<dim3(O_ / BN, T_ / BM), 128, GEMM_SMEM>>>(out);
}